// round 11
// baseline (speedup 1.0000x reference)
#include <cuda_runtime.h>
#include <cuda_fp16.h>
#include <cstdint>

// ===========================================================================
// AxialAttention via mma.sync fp16 m16n8k16 + ldmatrix, STREAM-K scheduled:
// grid = #SMs, each CTA processes an equal contiguous range of the global
// (tile, k-chunk) list with a continuous 3-stage cp.async pipeline across
// tile boundaries. Boundary tiles exchange fp32 partials via L2 scratch +
// per-tile atomic counters (owner gathers, then does the epilogue once).
//   QK  = Xh@[Wq;Wk]^T + [bq;bk]  [4096,2048] fp16
//   Vth = Wvh@Xh^T+bv             [1024,4096] fp16
//   P   = exp(Q@K^T/128) per batch, unnormalized fp16 (MODE 3) + rowsum atomics
//   Yh  = (P@Vt^T)/rowsum per batch, shuffle-stored (MODE 2)
//   out = Yh@Woh^T + bo (fp32)
// ===========================================================================

#define BK 64
#define ROW_BYTES 128
#define TM 128
#define TN 256
#define A_STG (TM * ROW_BYTES)        // 16 KB
#define B_STG (TN * ROW_BYTES)        // 32 KB
#define STAGES 3
#define SMEM_TOT (STAGES * (A_STG + B_STG))   // 144 KB -> 1 CTA/SM, all resident

// scratch
__device__ __half g_Xh[4096 * 1024];
__device__ __half g_Wh[4 * 1024 * 1024];
__device__ float  g_bqk[2048];
__device__ __half g_QK[4096 * 2048];
__device__ __half g_Vt[1024 * 4096];
__device__ __half g_P [2ll * 2048 * 2048];
__device__ __half g_Y [4096 * 1024];
__device__ float  g_rsum[2 * 2048];
__device__ float  g_part[200 * 256 * 128];   // per-CTA fp32 partial slot (128KB each)
__device__ int    g_cnt[512];                 // per-tile chunk counters (owner-reset)

__device__ __forceinline__ void mma_f16(float* d, const uint32_t* a,
                                        uint32_t b0, uint32_t b1) {
    asm volatile(
        "mma.sync.aligned.m16n8k16.row.col.f32.f16.f16.f32 "
        "{%0,%1,%2,%3}, {%4,%5,%6,%7}, {%8,%9}, {%0,%1,%2,%3};"
        : "+f"(d[0]), "+f"(d[1]), "+f"(d[2]), "+f"(d[3])
        : "r"(a[0]), "r"(a[1]), "r"(a[2]), "r"(a[3]), "r"(b0), "r"(b1));
}
__device__ __forceinline__ void ldsm4(uint32_t* r, uint32_t addr) {
    asm volatile("ldmatrix.sync.aligned.m8n8.x4.shared.b16 {%0,%1,%2,%3}, [%4];"
        : "=r"(r[0]), "=r"(r[1]), "=r"(r[2]), "=r"(r[3]) : "r"(addr));
}

#define CP_ASYNC(dst, src) \
    asm volatile("cp.async.cg.shared.global [%0], [%1], 16;" :: "r"(dst), \
                 "l"(__cvta_generic_to_global(src)))
#define CP_COMMIT() asm volatile("cp.async.commit_group;" ::: "memory")
#define CP_WAIT1()  asm volatile("cp.async.wait_group 1;" ::: "memory")

// ---------------------------------------------------------------------------
// MODE 0: plain store, bias by column.   MODE 1: plain store, bias by row.
// MODE 2: shuffle store (reference reshape), scaled by 1/rowsum[row].
// MODE 3: exp() store (unnormalized softmax), accumulate rowsum atomically.
// ---------------------------------------------------------------------------
template <int MODE, bool HALF_OUT>
__global__ void __launch_bounds__(256, 1) mma_gemm_sk(
    const __half* __restrict__ A, int lda, long long sA,
    const __half* __restrict__ B, int ldb, long long sB,
    const float* __restrict__ bias, float* __restrict__ rowsum,
    void* __restrict__ Cv, int ldC, long long sC,
    int nch, int gx, int gy, int q, int total_chunks, float alpha,
    float* __restrict__ part, int* __restrict__ cnt)
{
    extern __shared__ __align__(128) char smc[];

    int s = blockIdx.x * q;
    int E = min(s + q, total_chunks);
    if (s >= E) return;

    int tid = threadIdx.x, lane = tid & 31, wid = tid >> 5;
    int gr = lane >> 2, qc = lane & 3;
    int mw = (wid >> 2) * 64, nw = (wid & 3) * 64;

    uint32_t sA32 = (uint32_t)__cvta_generic_to_shared(smc);
    uint32_t sB32 = sA32 + STAGES * A_STG;

    int t8 = lane & 7, half8 = (lane >> 3) & 1, cg = lane >> 4;
    uint32_t aRow[4], aX7[4], bRow[4], bX7[4];
#pragma unroll
    for (int mf = 0; mf < 4; mf++) {
        int r = mw + mf * 16 + half8 * 8 + t8;
        aRow[mf] = (uint32_t)r * ROW_BYTES;
        aX7[mf] = (uint32_t)(r & 7);
    }
#pragma unroll
    for (int p = 0; p < 4; p++) {
        int r = nw + p * 16 + half8 * 8 + t8;
        bRow[p] = (uint32_t)r * ROW_BYTES;
        bX7[p] = (uint32_t)(r & 7);
    }
    int lr = tid >> 3;
    int lc = tid & 7;

    float acc[4][8][4];
#pragma unroll
    for (int i = 0; i < 4; i++)
#pragma unroll
        for (int j = 0; j < 8; j++)
#pragma unroll
            for (int t = 0; t < 4; t++) acc[i][j][t] = 0.f;

    // ---- tile cursors -----------------------------------------------------
    int ct = s / nch;                 // current tile index
    int c0 = s - ct * nch;            // my first chunk within current tile
    int tx = ct % gx, t2 = ct / gx, ty = t2 % gy, tz = t2 / gy;

    int pc = c0, px = tx, py = ty, pz = tz;        // prefetch cursor
    const __half* pAb = A + pz * sA + (long long)py * TM * lda;
    const __half* pBb = B + pz * sB + (long long)px * TN * ldb;

    auto load_stage = [&](int st) {
        long long ko = (long long)pc * BK + lc * 8;
#pragma unroll
        for (int it = 0; it < 4; it++) {
            int r = it * 32 + lr;
            uint32_t so = (uint32_t)(st * A_STG + r * ROW_BYTES +
                                     ((lc ^ (r & 7)) << 4));
            CP_ASYNC(sA32 + so, pAb + (long long)r * lda + ko);
        }
#pragma unroll
        for (int it = 0; it < 8; it++) {
            int r = it * 32 + lr;
            uint32_t so = (uint32_t)(st * B_STG + r * ROW_BYTES +
                                     ((lc ^ (r & 7)) << 4));
            CP_ASYNC(sB32 + so, pBb + (long long)r * ldb + ko);
        }
        // advance prefetch cursor
        if (++pc == nch) {
            pc = 0;
            if (++px == gx) { px = 0; if (++py == gy) { py = 0; pz++; } }
            pAb = A + pz * sA + (long long)py * TM * lda;
            pBb = B + pz * sB + (long long)px * TN * ldb;
        }
    };

    load_stage(0);
    CP_COMMIT();
    if (s + 1 < E) load_stage(1);
    CP_COMMIT();

    int st = 0;
    int cc = c0;                      // chunks computed so far in tile (end idx)
    for (int g = s; g < E; ++g) {
        CP_WAIT1();
        __syncthreads();
        if (g + 2 < E) load_stage((st + 2) % 3);
        CP_COMMIT();

        uint32_t stA = sA32 + st * A_STG;
        uint32_t stB = sB32 + st * B_STG;
#pragma unroll
        for (int ks = 0; ks < 4; ks++) {
            uint32_t c = (uint32_t)(ks * 2 + cg);
            uint32_t af[4][4], bb[4][4];
#pragma unroll
            for (int mf = 0; mf < 4; mf++)
                ldsm4(af[mf], stA + aRow[mf] + ((c ^ aX7[mf]) << 4));
#pragma unroll
            for (int p = 0; p < 4; p++)
                ldsm4(bb[p], stB + bRow[p] + ((c ^ bX7[p]) << 4));
#pragma unroll
            for (int mf = 0; mf < 4; mf++)
#pragma unroll
                for (int nf = 0; nf < 8; nf++)
                    mma_f16(acc[mf][nf], af[mf],
                            bb[nf >> 1][nf & 1], bb[nf >> 1][2 + (nf & 1)]);
        }
        st = (st + 1) % 3;
        cc++;

        if (cc == nch || g + 1 == E) {
            // ---------------- flush tile (ct, c0..cc) ----------------------
            bool do_epi = false;
            if (c0 == 0 && cc == nch) {
                do_epi = true;                       // full tile, direct
            } else if (c0 > 0) {
                // contributor: write fp32 partial to my slot, bump counter
                float* slot = part + (long long)blockIdx.x * (256 * 128) + tid * 128;
#pragma unroll
                for (int mf = 0; mf < 4; mf++)
#pragma unroll
                    for (int nf = 0; nf < 8; nf++) {
                        float4 v = { acc[mf][nf][0], acc[mf][nf][1],
                                     acc[mf][nf][2], acc[mf][nf][3] };
                        __stcg((float4*)(slot + (mf * 8 + nf) * 4), v);
                    }
                __threadfence();
                __syncthreads();
                if (tid == 0) atomicAdd(&cnt[ct], cc - c0);
            } else {
                // owner of a split tile: wait for the remaining chunks
                int need = nch - cc;
                int cA = (ct * nch + cc) / q;
                int cB = (ct * nch + nch - 1) / q;
                if (tid == 0) {
                    while (atomicAdd(&cnt[ct], 0) != need) { }
                }
                __syncthreads();
                __threadfence();
                for (int cta = cA; cta <= cB; cta++) {
                    const float* slot = part + (long long)cta * (256 * 128) + tid * 128;
#pragma unroll
                    for (int mf = 0; mf < 4; mf++)
#pragma unroll
                        for (int nf = 0; nf < 8; nf++) {
                            float4 v = __ldcg((const float4*)(slot + (mf * 8 + nf) * 4));
                            acc[mf][nf][0] += v.x; acc[mf][nf][1] += v.y;
                            acc[mf][nf][2] += v.z; acc[mf][nf][3] += v.w;
                        }
                }
                __syncthreads();
                if (tid == 0) atomicExch(&cnt[ct], 0);   // reset for next run
                do_epi = true;
            }

            if (do_epi) {
#pragma unroll
                for (int mf = 0; mf < 4; mf++) {
                    int row = ty * TM + mw + mf * 16 + gr;
                    float sum0 = 0.f, sum1 = 0.f;
                    float inv0 = 1.f, inv1 = 1.f;
                    if (MODE == 2) {
                        const float* rs = rowsum + tz * 2048;
                        inv0 = 1.0f / rs[row];
                        inv1 = 1.0f / rs[row + 8];
                    }
#pragma unroll
                    for (int nf = 0; nf < 8; nf++) {
                        int col = tx * TN + nw + nf * 8 + 2 * qc;
                        float v0 = acc[mf][nf][0] * alpha;
                        float v1 = acc[mf][nf][1] * alpha;
                        float v2 = acc[mf][nf][2] * alpha;
                        float v3 = acc[mf][nf][3] * alpha;
                        if (MODE == 0 && bias) {
                            float b0 = bias[col], b1 = bias[col + 1];
                            v0 += b0; v1 += b1; v2 += b0; v3 += b1;
                        }
                        if (MODE == 1) {
                            float b0 = bias[row], b1 = bias[row + 8];
                            v0 += b0; v1 += b0; v2 += b1; v3 += b1;
                        }
                        if (MODE == 2) {
                            v0 *= inv0; v1 *= inv0; v2 *= inv1; v3 *= inv1;
                        }
                        if (MODE == 3) {
                            v0 = __expf(v0); v1 = __expf(v1);
                            v2 = __expf(v2); v3 = __expf(v3);
                            sum0 += v0 + v1; sum1 += v2 + v3;
                        }
                        long long o0, o1;
                        if (MODE == 2) {
                            int h = col >> 6, d0 = col & 63;
                            o0 = (long long)(h * 128 + (row >> 4)) * 1024 +
                                 ((row & 15) << 6) + d0;
                            int row2 = row + 8;
                            o1 = (long long)(h * 128 + (row2 >> 4)) * 1024 +
                                 ((row2 & 15) << 6) + d0;
                        } else {
                            o0 = (long long)row * ldC + col;
                            o1 = o0 + 8ll * ldC;
                        }
                        if (HALF_OUT) {
                            __half* Cb = (__half*)Cv + tz * sC;
                            *(__half2*)(Cb + o0) = __floats2half2_rn(v0, v1);
                            *(__half2*)(Cb + o1) = __floats2half2_rn(v2, v3);
                        } else {
                            float* Cb = (float*)Cv + tz * sC;
                            *(float2*)(Cb + o0) = make_float2(v0, v1);
                            *(float2*)(Cb + o1) = make_float2(v2, v3);
                        }
                    }
                    if (MODE == 3) {
                        sum0 += __shfl_xor_sync(0xffffffffu, sum0, 1);
                        sum0 += __shfl_xor_sync(0xffffffffu, sum0, 2);
                        sum1 += __shfl_xor_sync(0xffffffffu, sum1, 1);
                        sum1 += __shfl_xor_sync(0xffffffffu, sum1, 2);
                        if (qc == 0) {
                            float* rs = rowsum + tz * 2048;
                            atomicAdd(rs + row, sum0);
                            atomicAdd(rs + row + 8, sum1);
                        }
                    }
                }
            }

            // advance to next tile, clear acc
            ct++; c0 = 0; cc = 0;
            if (++tx == gx) { tx = 0; if (++ty == gy) { ty = 0; tz++; } }
#pragma unroll
            for (int i = 0; i < 4; i++)
#pragma unroll
                for (int j = 0; j < 8; j++)
#pragma unroll
                    for (int t = 0; t < 4; t++) acc[i][j][t] = 0.f;
        }
    }
}

// ---------------------------------------------------------------------------
// fused fp32->fp16 conversion + bias concat + rowsum zeroing
// ---------------------------------------------------------------------------
__global__ __launch_bounds__(256) void f2h_all(
    const float4* __restrict__ x,
    const float4* __restrict__ w0, const float4* __restrict__ w1,
    const float4* __restrict__ w2, const float4* __restrict__ w3,
    const float* __restrict__ bq, const float* __restrict__ bk,
    __half* __restrict__ Xh, __half* __restrict__ Wh,
    float* __restrict__ bqk, float* __restrict__ rsum)
{
    int i = blockIdx.x * 256 + threadIdx.x;
    if (i < 2048) bqk[i] = (i < 1024) ? bq[i] : bk[i - 1024];
    if (i < 4096) rsum[i] = 0.f;
    const float4* src;
    __half* dst;
    if (i < (1 << 20)) { src = x + i; dst = Xh + (long long)i * 4; }
    else {
        int j = i - (1 << 20);
        int w = j >> 18, off = j & ((1 << 18) - 1);
        const float4* ws[4] = {w0, w1, w2, w3};
        src = ws[w] + off;
        dst = Wh + ((long long)w << 20) + (long long)off * 4;
    }
    float4 v = *src;
    __half2 h0 = __floats2half2_rn(v.x, v.y);
    __half2 h1 = __floats2half2_rn(v.z, v.w);
    *(uint2*)dst = make_uint2(*(uint32_t*)&h0, *(uint32_t*)&h1);
}

// ---------------------------------------------------------------------------
extern "C" void kernel_launch(void* const* d_in, const int* in_sizes, int n_in,
                              void* d_out, int out_size)
{
    const float* x  = (const float*)d_in[0];
    const float* bq = (const float*)d_in[2];
    const float* bk = (const float*)d_in[4];
    const float* bv = (const float*)d_in[6];
    const float* bo = (const float*)d_in[8];
    float* out = (float*)d_out;

    __half *Xh, *Wh, *QK, *Vt, *P, *Y;
    float *bqk, *rsum, *partp;
    int *cntp;
    cudaGetSymbolAddress((void**)&Xh,    g_Xh);
    cudaGetSymbolAddress((void**)&Wh,    g_Wh);
    cudaGetSymbolAddress((void**)&QK,    g_QK);
    cudaGetSymbolAddress((void**)&Vt,    g_Vt);
    cudaGetSymbolAddress((void**)&P,     g_P);
    cudaGetSymbolAddress((void**)&Y,     g_Y);
    cudaGetSymbolAddress((void**)&bqk,   g_bqk);
    cudaGetSymbolAddress((void**)&rsum,  g_rsum);
    cudaGetSymbolAddress((void**)&partp, g_part);
    cudaGetSymbolAddress((void**)&cntp,  g_cnt);

    int NSM = 148;
    cudaDeviceGetAttribute(&NSM, cudaDevAttrMultiProcessorCount, 0);
    if (NSM > 200) NSM = 200;     // scratch slot bound

    cudaFuncSetAttribute(mma_gemm_sk<0, true>,  cudaFuncAttributeMaxDynamicSharedMemorySize, SMEM_TOT);
    cudaFuncSetAttribute(mma_gemm_sk<0, false>, cudaFuncAttributeMaxDynamicSharedMemorySize, SMEM_TOT);
    cudaFuncSetAttribute(mma_gemm_sk<1, true>,  cudaFuncAttributeMaxDynamicSharedMemorySize, SMEM_TOT);
    cudaFuncSetAttribute(mma_gemm_sk<2, true>,  cudaFuncAttributeMaxDynamicSharedMemorySize, SMEM_TOT);
    cudaFuncSetAttribute(mma_gemm_sk<3, true>,  cudaFuncAttributeMaxDynamicSharedMemorySize, SMEM_TOT);

    f2h_all<<<8192, 256>>>((const float4*)x,
                           (const float4*)d_in[1], (const float4*)d_in[3],
                           (const float4*)d_in[5], (const float4*)d_in[7],
                           bq, bk, Xh, Wh, bqk, rsum);

    dim3 blk(256);

    // helper: chunk-balanced launch params
    auto QOF = [&](int tiles, int nch, int& q, int& grid, int& total) {
        total = tiles * nch;
        q = (total + NSM - 1) / NSM;
        grid = (total + q - 1) / q;
    };
    int q, grid, total;

    // QK = Xh @ [Wq;Wk]^T + [bq;bk] -> fp16 [4096,2048]   gx=8, gy=32, nch=16
    QOF(8 * 32, 16, q, grid, total);
    mma_gemm_sk<0, true><<<grid, blk, SMEM_TOT>>>(
        Xh, 1024, 0, Wh, 1024, 0, bqk, nullptr, QK, 2048, 0,
        16, 8, 32, q, total, 1.f, partp, cntp);

    // Vt = Wv @ Xh^T + bv -> fp16 [1024,4096]   gx=16, gy=8, nch=16
    QOF(16 * 8, 16, q, grid, total);
    mma_gemm_sk<1, true><<<grid, blk, SMEM_TOT>>>(
        Wh + 2097152, 1024, 0, Xh, 1024, 0, bv, nullptr, Vt, 4096, 0,
        16, 16, 8, q, total, 1.f, partp, cntp);

    // P = exp(Q @ K^T / 128) per batch -> fp16 [2,2048,2048]   gx=8, gy=16, z=2
    QOF(8 * 16 * 2, 16, q, grid, total);
    mma_gemm_sk<3, true><<<grid, blk, SMEM_TOT>>>(
        QK, 2048, 2048ll * 2048, QK + 1024, 2048, 2048ll * 2048,
        nullptr, rsum, P, 2048, 2048ll * 2048,
        16, 8, 16, q, total, 1.f / 128.f, partp, cntp);

    // Y = (P @ Vt^T) / rowsum per batch, shuffled -> fp16   gx=4, gy=16, z=2, nch=32
    QOF(4 * 16 * 2, 32, q, grid, total);
    mma_gemm_sk<2, true><<<grid, blk, SMEM_TOT>>>(
        P, 2048, 2048ll * 2048, Vt, 4096, 2048,
        nullptr, rsum, Y, 1024, 2048ll * 1024,
        32, 4, 16, q, total, 1.f, partp, cntp);

    // out = Y @ Wo^T + bo -> fp32 [4096,1024]   gx=4, gy=32
    QOF(4 * 32, 16, q, grid, total);
    mma_gemm_sk<0, false><<<grid, blk, SMEM_TOT>>>(
        Y, 1024, 0, Wh + 3145728, 1024, 0, bo, nullptr, out, 1024, 0,
        16, 4, 32, q, total, 1.f, partp, cntp);
}

// round 12
// speedup vs baseline: 1.1969x; 1.1969x over previous
#include <cuda_runtime.h>
#include <cuda_fp16.h>
#include <cstdint>

// ===========================================================================
// AxialAttention via mma.sync fp16 m16n8k16 + ldmatrix; 3-stage cp.async,
// 2 CTAs/SM (R9 structure). QK and Vt projections (independent) FUSED into one
// 768-CTA launch for wave packing. Softmax fused into GEMM epilogues.
//   QK  = Xh@[Wq;Wk]^T + [bq;bk]  [4096,2048] fp16
//   Vth = Wvh@Xh^T+bv             [1024,4096] fp16
//   P   = exp(Q@K^T/128) per batch, unnormalized fp16 (MODE 3) + rowsum atomics
//   Yh  = (P@Vt^T)/rowsum per batch, shuffle-stored (MODE 2)
//   out = Yh@Woh^T + bo (fp32)
// ===========================================================================

#define BK 64
#define ROW_BYTES 128
#define STG_BYTES (128 * ROW_BYTES)   // 16 KB
#define STAGES 3
#define SMEM_TOT (2 * STAGES * STG_BYTES)  // 96 KB -> 2 CTAs/SM

// scratch
__device__ __half g_Xh[4096 * 1024];
__device__ __half g_Wh[4 * 1024 * 1024];
__device__ float  g_bqk[2048];
__device__ __half g_QK[4096 * 2048];
__device__ __half g_Vt[1024 * 4096];
__device__ __half g_P [2ll * 2048 * 2048];
__device__ __half g_Y [4096 * 1024];
__device__ float  g_rsum[2 * 2048];

__device__ __forceinline__ void mma_f16(float* d, const uint32_t* a,
                                        uint32_t b0, uint32_t b1) {
    asm volatile(
        "mma.sync.aligned.m16n8k16.row.col.f32.f16.f16.f32 "
        "{%0,%1,%2,%3}, {%4,%5,%6,%7}, {%8,%9}, {%0,%1,%2,%3};"
        : "+f"(d[0]), "+f"(d[1]), "+f"(d[2]), "+f"(d[3])
        : "r"(a[0]), "r"(a[1]), "r"(a[2]), "r"(a[3]), "r"(b0), "r"(b1));
}
__device__ __forceinline__ void ldsm4(uint32_t* r, uint32_t addr) {
    asm volatile("ldmatrix.sync.aligned.m8n8.x4.shared.b16 {%0,%1,%2,%3}, [%4];"
        : "=r"(r[0]), "=r"(r[1]), "=r"(r[2]), "=r"(r[3]) : "r"(addr));
}

#define CP_ASYNC(dst, src) \
    asm volatile("cp.async.cg.shared.global [%0], [%1], 16;" :: "r"(dst), \
                 "l"(__cvta_generic_to_global(src)))
#define CP_COMMIT() asm volatile("cp.async.commit_group;" ::: "memory")
#define CP_WAIT1()  asm volatile("cp.async.wait_group 1;" ::: "memory")

// ---------------------------------------------------------------------------
// GEMM body: 128x128 tile, 8 warps (64x32 warp tiles), 3-stage cp.async.
// MODE 0: plain store, bias by column.   MODE 1: plain store, bias by row.
// MODE 2: shuffle store (reference reshape), scaled by 1/rowsum[row].
// MODE 3: exp() store (unnormalized softmax), accumulate rowsum atomically.
// ---------------------------------------------------------------------------
template <int MODE, bool HALF_OUT>
__device__ __forceinline__ void gemm_body(
    const __half* __restrict__ A, int lda, long long sA,
    const __half* __restrict__ B, int ldb, long long sB,
    const float* __restrict__ bias, float* __restrict__ rowsum,
    void* __restrict__ Cv, int ldC, long long sC,
    int nch, float alpha, int bx, int by, int bz)
{
    extern __shared__ __align__(128) char smc[];

    const __half* Ab = A + bz * sA + (long long)by * 128 * lda;
    const __half* Bb = B + bz * sB + (long long)bx * 128 * ldb;

    int tid = threadIdx.x, lane = tid & 31, wid = tid >> 5;
    int gr = lane >> 2, qc = lane & 3;
    int mw = (wid >> 2) * 64, nw = (wid & 3) * 32;

    uint32_t sA32 = (uint32_t)__cvta_generic_to_shared(smc);
    uint32_t sB32 = sA32 + STAGES * STG_BYTES;

    int t8 = lane & 7, half8 = (lane >> 3) & 1, cg = lane >> 4;
    uint32_t aRow[4], aX7[4], bRow[2], bX7[2];
#pragma unroll
    for (int mf = 0; mf < 4; mf++) {
        int r = mw + mf * 16 + half8 * 8 + t8;
        aRow[mf] = (uint32_t)r * ROW_BYTES;
        aX7[mf] = (uint32_t)(r & 7);
    }
#pragma unroll
    for (int p = 0; p < 2; p++) {
        int r = nw + p * 16 + half8 * 8 + t8;
        bRow[p] = (uint32_t)r * ROW_BYTES;
        bX7[p] = (uint32_t)(r & 7);
    }

    int lr = tid >> 3;
    int lc = tid & 7;

    float acc[4][4][4];
#pragma unroll
    for (int i = 0; i < 4; i++)
#pragma unroll
        for (int j = 0; j < 4; j++)
#pragma unroll
            for (int t = 0; t < 4; t++) acc[i][j][t] = 0.f;

    auto load_stage = [&](int ch, int st) {
        long long ko = (long long)ch * BK + lc * 8;
#pragma unroll
        for (int it = 0; it < 4; it++) {
            int r = it * 32 + lr;
            uint32_t so = (uint32_t)(st * STG_BYTES + r * ROW_BYTES +
                                     ((lc ^ (r & 7)) << 4));
            CP_ASYNC(sA32 + so, Ab + (long long)r * lda + ko);
            CP_ASYNC(sB32 + so, Bb + (long long)r * ldb + ko);
        }
    };

    load_stage(0, 0);
    CP_COMMIT();
    load_stage(1, 1);
    CP_COMMIT();

    int st = 0;
    for (int ch = 0; ch < nch; ch++) {
        CP_WAIT1();
        __syncthreads();
        if (ch + 2 < nch) load_stage(ch + 2, (ch + 2) % STAGES);
        CP_COMMIT();

        uint32_t stA = sA32 + st * STG_BYTES;
        uint32_t stB = sB32 + st * STG_BYTES;
        if (++st == STAGES) st = 0;
#pragma unroll
        for (int ks = 0; ks < 4; ks++) {
            uint32_t c = (uint32_t)(ks * 2 + cg);
            uint32_t af[4][4], bb[2][4];
#pragma unroll
            for (int mf = 0; mf < 4; mf++)
                ldsm4(af[mf], stA + aRow[mf] + ((c ^ aX7[mf]) << 4));
#pragma unroll
            for (int p = 0; p < 2; p++)
                ldsm4(bb[p], stB + bRow[p] + ((c ^ bX7[p]) << 4));
#pragma unroll
            for (int mf = 0; mf < 4; mf++)
#pragma unroll
                for (int nf = 0; nf < 4; nf++)
                    mma_f16(acc[mf][nf], af[mf],
                            bb[nf >> 1][nf & 1], bb[nf >> 1][2 + (nf & 1)]);
        }
    }

    // epilogue
#pragma unroll
    for (int mf = 0; mf < 4; mf++) {
        int row = by * 128 + mw + mf * 16 + gr;
        float sum0 = 0.f, sum1 = 0.f;
        float inv0 = 1.f, inv1 = 1.f;
        if (MODE == 2) {
            const float* rs = rowsum + bz * 2048;
            inv0 = 1.0f / rs[row];
            inv1 = 1.0f / rs[row + 8];
        }
#pragma unroll
        for (int nf = 0; nf < 4; nf++) {
            int col = bx * 128 + nw + nf * 8 + 2 * qc;
            float v0 = acc[mf][nf][0] * alpha;
            float v1 = acc[mf][nf][1] * alpha;
            float v2 = acc[mf][nf][2] * alpha;
            float v3 = acc[mf][nf][3] * alpha;
            if (MODE == 0 && bias) {
                float b0 = bias[col], b1 = bias[col + 1];
                v0 += b0; v1 += b1; v2 += b0; v3 += b1;
            }
            if (MODE == 1) {
                float b0 = bias[row], b1 = bias[row + 8];
                v0 += b0; v1 += b0; v2 += b1; v3 += b1;
            }
            if (MODE == 2) {
                v0 *= inv0; v1 *= inv0; v2 *= inv1; v3 *= inv1;
            }
            if (MODE == 3) {
                v0 = __expf(v0); v1 = __expf(v1);
                v2 = __expf(v2); v3 = __expf(v3);
                sum0 += v0 + v1; sum1 += v2 + v3;
            }
            long long o0, o1;
            if (MODE == 2) {
                int h = col >> 6, d0 = col & 63;
                o0 = (long long)(h * 128 + (row >> 4)) * 1024 + ((row & 15) << 6) + d0;
                int row2 = row + 8;
                o1 = (long long)(h * 128 + (row2 >> 4)) * 1024 + ((row2 & 15) << 6) + d0;
            } else {
                o0 = (long long)row * ldC + col;
                o1 = o0 + 8ll * ldC;
            }
            if (HALF_OUT) {
                __half* Cb = (__half*)Cv + bz * sC;
                *(__half2*)(Cb + o0) = __floats2half2_rn(v0, v1);
                *(__half2*)(Cb + o1) = __floats2half2_rn(v2, v3);
            } else {
                float* Cb = (float*)Cv + bz * sC;
                *(float2*)(Cb + o0) = make_float2(v0, v1);
                *(float2*)(Cb + o1) = make_float2(v2, v3);
            }
        }
        if (MODE == 3) {
            sum0 += __shfl_xor_sync(0xffffffffu, sum0, 1);
            sum0 += __shfl_xor_sync(0xffffffffu, sum0, 2);
            sum1 += __shfl_xor_sync(0xffffffffu, sum1, 1);
            sum1 += __shfl_xor_sync(0xffffffffu, sum1, 2);
            if (qc == 0) {
                float* rs = rowsum + bz * 2048;
                atomicAdd(rs + row, sum0);
                atomicAdd(rs + row + 8, sum1);
            }
        }
    }
}

// plain wrapper kernels
template <int MODE, bool HALF_OUT>
__global__ void __launch_bounds__(256, 2) mma_gemm(
    const __half* __restrict__ A, int lda, long long sA,
    const __half* __restrict__ B, int ldb, long long sB,
    const float* __restrict__ bias, float* __restrict__ rowsum,
    void* __restrict__ Cv, int ldC, long long sC,
    int nch, float alpha)
{
    gemm_body<MODE, HALF_OUT>(A, lda, sA, B, ldb, sB, bias, rowsum,
                              Cv, ldC, sC, nch, alpha,
                              blockIdx.x, blockIdx.y, blockIdx.z);
}

// fused QK (512 tiles, MODE 0) + Vt (256 tiles, MODE 1) launch: grid 768
__global__ void __launch_bounds__(256, 2) qkvt_fused(
    const __half* __restrict__ Xh, const __half* __restrict__ Wqk,
    const float* __restrict__ bqk, __half* __restrict__ QK,
    const __half* __restrict__ Wv, const float* __restrict__ bv,
    __half* __restrict__ Vt)
{
    int b = blockIdx.x;
    if (b < 512) {
        // QK = Xh[4096,1024] @ Wqk[2048,1024]^T : gx=16, gy=32
        gemm_body<0, true>(Xh, 1024, 0, Wqk, 1024, 0, bqk, nullptr,
                           QK, 2048, 0, 16, 1.f, b & 15, b >> 4, 0);
    } else {
        // Vt = Wv[1024,1024] @ Xh[4096,1024]^T : gx=32, gy=8
        b -= 512;
        gemm_body<1, true>(Wv, 1024, 0, Xh, 1024, 0, bv, nullptr,
                           Vt, 4096, 0, 16, 1.f, b & 31, b >> 5, 0);
    }
}

// ---------------------------------------------------------------------------
// fused fp32->fp16 conversion + bias concat + rowsum zeroing
// ---------------------------------------------------------------------------
__global__ __launch_bounds__(256) void f2h_all(
    const float4* __restrict__ x,
    const float4* __restrict__ w0, const float4* __restrict__ w1,
    const float4* __restrict__ w2, const float4* __restrict__ w3,
    const float* __restrict__ bq, const float* __restrict__ bk,
    __half* __restrict__ Xh, __half* __restrict__ Wh,
    float* __restrict__ bqk, float* __restrict__ rsum)
{
    int i = blockIdx.x * 256 + threadIdx.x;
    if (i < 2048) bqk[i] = (i < 1024) ? bq[i] : bk[i - 1024];
    if (i < 4096) rsum[i] = 0.f;
    const float4* src;
    __half* dst;
    if (i < (1 << 20)) { src = x + i; dst = Xh + (long long)i * 4; }
    else {
        int j = i - (1 << 20);
        int w = j >> 18, off = j & ((1 << 18) - 1);
        const float4* ws[4] = {w0, w1, w2, w3};
        src = ws[w] + off;
        dst = Wh + ((long long)w << 20) + (long long)off * 4;
    }
    float4 v = *src;
    __half2 h0 = __floats2half2_rn(v.x, v.y);
    __half2 h1 = __floats2half2_rn(v.z, v.w);
    *(uint2*)dst = make_uint2(*(uint32_t*)&h0, *(uint32_t*)&h1);
}

// ---------------------------------------------------------------------------
extern "C" void kernel_launch(void* const* d_in, const int* in_sizes, int n_in,
                              void* d_out, int out_size)
{
    const float* x  = (const float*)d_in[0];
    const float* bq = (const float*)d_in[2];
    const float* bk = (const float*)d_in[4];
    const float* bv = (const float*)d_in[6];
    const float* bo = (const float*)d_in[8];
    float* out = (float*)d_out;

    __half *Xh, *Wh, *QK, *Vt, *P, *Y;
    float *bqk, *rsum;
    cudaGetSymbolAddress((void**)&Xh,   g_Xh);
    cudaGetSymbolAddress((void**)&Wh,   g_Wh);
    cudaGetSymbolAddress((void**)&QK,   g_QK);
    cudaGetSymbolAddress((void**)&Vt,   g_Vt);
    cudaGetSymbolAddress((void**)&P,    g_P);
    cudaGetSymbolAddress((void**)&Y,    g_Y);
    cudaGetSymbolAddress((void**)&bqk,  g_bqk);
    cudaGetSymbolAddress((void**)&rsum, g_rsum);

    cudaFuncSetAttribute(qkvt_fused,         cudaFuncAttributeMaxDynamicSharedMemorySize, SMEM_TOT);
    cudaFuncSetAttribute(mma_gemm<0, false>, cudaFuncAttributeMaxDynamicSharedMemorySize, SMEM_TOT);
    cudaFuncSetAttribute(mma_gemm<2, true>,  cudaFuncAttributeMaxDynamicSharedMemorySize, SMEM_TOT);
    cudaFuncSetAttribute(mma_gemm<3, true>,  cudaFuncAttributeMaxDynamicSharedMemorySize, SMEM_TOT);

    f2h_all<<<8192, 256>>>((const float4*)x,
                           (const float4*)d_in[1], (const float4*)d_in[3],
                           (const float4*)d_in[5], (const float4*)d_in[7],
                           bq, bk, Xh, Wh, bqk, rsum);

    dim3 blk(256);

    // QK + Vt fused (wave packing): 512 QK tiles then 256 Vt tiles
    qkvt_fused<<<768, blk, SMEM_TOT>>>(Xh, Wh, bqk, QK, Wh + 2097152, bv, Vt);

    // P = exp(Q @ K^T / 128) per batch -> fp16 [2,2048,2048], rowsums accumulated
    mma_gemm<3, true><<<dim3(16, 16, 2), blk, SMEM_TOT>>>(
        QK, 2048, 2048ll * 2048, QK + 1024, 2048, 2048ll * 2048,
        nullptr, rsum, P, 2048, 2048ll * 2048, 16, 1.f / 128.f);

    // Y = (P @ Vt^T) / rowsum per batch, shuffled -> fp16 [4096,1024]
    mma_gemm<2, true><<<dim3(8, 16, 2), blk, SMEM_TOT>>>(
        P, 2048, 2048ll * 2048, Vt, 4096, 2048,
        nullptr, rsum, Y, 1024, 2048ll * 1024, 32, 1.f);

    // out = Y @ Wo^T + bo -> fp32
    mma_gemm<0, false><<<dim3(8, 32, 1), blk, SMEM_TOT>>>(
        Y, 1024, 0, Wh + 3145728, 1024, 0, bo, nullptr, out, 1024, 0, 16, 1.f);
}

// round 13
// speedup vs baseline: 1.2667x; 1.0583x over previous
#include <cuda_runtime.h>
#include <cuda_fp16.h>
#include <cstdint>

// ===========================================================================
// AxialAttention: ONE persistent DAG-scheduled kernel runs all 5 GEMMs
// (mma.sync fp16 m16n8k16 + ldmatrix, 3-stage cp.async, 2 CTAs/SM).
// Global work queue of 2048 tile-items in dependency order; per-row-block
// completion counters gate consumers (spin+nanosleep). Softmax fused.
//   QK  = Xh@[Wq;Wk]^T + [bq;bk]  [4096,2048] fp16          items 0..511
//   Vth = Wvh@Xh^T+bv             [1024,4096] fp16          items 512..767
//   P   = exp(Q@K^T/128), unnorm fp16 + rowsum atomics      items 768..1279
//   Yh  = (P@Vt^T)/rowsum, shuffle-stored                   items 1280..1535
//   out = Yh@Woh^T + bo (fp32)                              items 1536..1791
// ===========================================================================

#define BK 64
#define ROW_BYTES 128
#define STG_BYTES (128 * ROW_BYTES)   // 16 KB
#define STAGES 3
#define SMEM_TOT (2 * STAGES * STG_BYTES)  // 96 KB -> 2 CTAs/SM
#define N_ITEMS 1792

// scratch
__device__ __half g_Xh[4096 * 1024];
__device__ __half g_Wh[4 * 1024 * 1024];
__device__ float  g_bqk[2048];
__device__ __half g_QK[4096 * 2048];
__device__ __half g_Vt[1024 * 4096];
__device__ __half g_P [2ll * 2048 * 2048];
__device__ __half g_Y [4096 * 1024];
__device__ float  g_rsum[2 * 2048];
// sync[0]=queue head; [1..32]=QK rows; [33..40]=Vt rows; [41..72]=S rows; [73..88]=PV colpairs
__device__ int    g_sync[128];

__device__ __forceinline__ void mma_f16(float* d, const uint32_t* a,
                                        uint32_t b0, uint32_t b1) {
    asm volatile(
        "mma.sync.aligned.m16n8k16.row.col.f32.f16.f16.f32 "
        "{%0,%1,%2,%3}, {%4,%5,%6,%7}, {%8,%9}, {%0,%1,%2,%3};"
        : "+f"(d[0]), "+f"(d[1]), "+f"(d[2]), "+f"(d[3])
        : "r"(a[0]), "r"(a[1]), "r"(a[2]), "r"(a[3]), "r"(b0), "r"(b1));
}
__device__ __forceinline__ void ldsm4(uint32_t* r, uint32_t addr) {
    asm volatile("ldmatrix.sync.aligned.m8n8.x4.shared.b16 {%0,%1,%2,%3}, [%4];"
        : "=r"(r[0]), "=r"(r[1]), "=r"(r[2]), "=r"(r[3]) : "r"(addr));
}

#define CP_ASYNC(dst, src) \
    asm volatile("cp.async.cg.shared.global [%0], [%1], 16;" :: "r"(dst), \
                 "l"(__cvta_generic_to_global(src)))
#define CP_COMMIT() asm volatile("cp.async.commit_group;" ::: "memory")
#define CP_WAIT1()  asm volatile("cp.async.wait_group 1;" ::: "memory")

// consumer: wait until *c >= need (tid0 spins), then acquire for whole CTA
__device__ __forceinline__ void waitcnt(int* c, int need) {
    if (threadIdx.x == 0) {
        while (atomicAdd(c, 0) < need) __nanosleep(128);
        __threadfence();
    }
    __syncthreads();
}
// producer: make all stores visible, then bump counter
__device__ __forceinline__ void donecnt(int* c) {
    __threadfence();
    __syncthreads();
    if (threadIdx.x == 0) atomicAdd(c, 1);
}

// ---------------------------------------------------------------------------
// GEMM body (unchanged saturated mainloop): 128x128 tile, 8 warps, 3 stages.
// MODE 0: plain store, bias by column.   MODE 1: plain store, bias by row.
// MODE 2: shuffle store (reference reshape), scaled by 1/rowsum[row].
// MODE 3: exp() store (unnormalized softmax), accumulate rowsum atomically.
// ---------------------------------------------------------------------------
template <int MODE, bool HALF_OUT>
__device__ __forceinline__ void gemm_body(
    const __half* __restrict__ A, int lda, long long sA,
    const __half* __restrict__ B, int ldb, long long sB,
    const float* __restrict__ bias, float* __restrict__ rowsum,
    void* __restrict__ Cv, int ldC, long long sC,
    int nch, float alpha, int bx, int by, int bz)
{
    extern __shared__ __align__(128) char smc[];

    const __half* Ab = A + bz * sA + (long long)by * 128 * lda;
    const __half* Bb = B + bz * sB + (long long)bx * 128 * ldb;

    int tid = threadIdx.x, lane = tid & 31, wid = tid >> 5;
    int gr = lane >> 2, qc = lane & 3;
    int mw = (wid >> 2) * 64, nw = (wid & 3) * 32;

    uint32_t sA32 = (uint32_t)__cvta_generic_to_shared(smc);
    uint32_t sB32 = sA32 + STAGES * STG_BYTES;

    int t8 = lane & 7, half8 = (lane >> 3) & 1, cg = lane >> 4;
    uint32_t aRow[4], aX7[4], bRow[2], bX7[2];
#pragma unroll
    for (int mf = 0; mf < 4; mf++) {
        int r = mw + mf * 16 + half8 * 8 + t8;
        aRow[mf] = (uint32_t)r * ROW_BYTES;
        aX7[mf] = (uint32_t)(r & 7);
    }
#pragma unroll
    for (int p = 0; p < 2; p++) {
        int r = nw + p * 16 + half8 * 8 + t8;
        bRow[p] = (uint32_t)r * ROW_BYTES;
        bX7[p] = (uint32_t)(r & 7);
    }

    int lr = tid >> 3;
    int lc = tid & 7;

    float acc[4][4][4];
#pragma unroll
    for (int i = 0; i < 4; i++)
#pragma unroll
        for (int j = 0; j < 4; j++)
#pragma unroll
            for (int t = 0; t < 4; t++) acc[i][j][t] = 0.f;

    auto load_stage = [&](int ch, int st) {
        long long ko = (long long)ch * BK + lc * 8;
#pragma unroll
        for (int it = 0; it < 4; it++) {
            int r = it * 32 + lr;
            uint32_t so = (uint32_t)(st * STG_BYTES + r * ROW_BYTES +
                                     ((lc ^ (r & 7)) << 4));
            CP_ASYNC(sA32 + so, Ab + (long long)r * lda + ko);
            CP_ASYNC(sB32 + so, Bb + (long long)r * ldb + ko);
        }
    };

    load_stage(0, 0);
    CP_COMMIT();
    load_stage(1, 1);
    CP_COMMIT();

    int st = 0;
    for (int ch = 0; ch < nch; ch++) {
        CP_WAIT1();
        __syncthreads();
        if (ch + 2 < nch) load_stage(ch + 2, (ch + 2) % STAGES);
        CP_COMMIT();

        uint32_t stA = sA32 + st * STG_BYTES;
        uint32_t stB = sB32 + st * STG_BYTES;
        if (++st == STAGES) st = 0;
#pragma unroll
        for (int ks = 0; ks < 4; ks++) {
            uint32_t c = (uint32_t)(ks * 2 + cg);
            uint32_t af[4][4], bb[2][4];
#pragma unroll
            for (int mf = 0; mf < 4; mf++)
                ldsm4(af[mf], stA + aRow[mf] + ((c ^ aX7[mf]) << 4));
#pragma unroll
            for (int p = 0; p < 2; p++)
                ldsm4(bb[p], stB + bRow[p] + ((c ^ bX7[p]) << 4));
#pragma unroll
            for (int mf = 0; mf < 4; mf++)
#pragma unroll
                for (int nf = 0; nf < 4; nf++)
                    mma_f16(acc[mf][nf], af[mf],
                            bb[nf >> 1][nf & 1], bb[nf >> 1][2 + (nf & 1)]);
        }
    }

    // epilogue
#pragma unroll
    for (int mf = 0; mf < 4; mf++) {
        int row = by * 128 + mw + mf * 16 + gr;
        float sum0 = 0.f, sum1 = 0.f;
        float inv0 = 1.f, inv1 = 1.f;
        if (MODE == 2) {
            const float* rs = rowsum + bz * 2048;
            inv0 = 1.0f / rs[row];
            inv1 = 1.0f / rs[row + 8];
        }
#pragma unroll
        for (int nf = 0; nf < 4; nf++) {
            int col = bx * 128 + nw + nf * 8 + 2 * qc;
            float v0 = acc[mf][nf][0] * alpha;
            float v1 = acc[mf][nf][1] * alpha;
            float v2 = acc[mf][nf][2] * alpha;
            float v3 = acc[mf][nf][3] * alpha;
            if (MODE == 0 && bias) {
                float b0 = bias[col], b1 = bias[col + 1];
                v0 += b0; v1 += b1; v2 += b0; v3 += b1;
            }
            if (MODE == 1) {
                float b0 = bias[row], b1 = bias[row + 8];
                v0 += b0; v1 += b0; v2 += b1; v3 += b1;
            }
            if (MODE == 2) {
                v0 *= inv0; v1 *= inv0; v2 *= inv1; v3 *= inv1;
            }
            if (MODE == 3) {
                v0 = __expf(v0); v1 = __expf(v1);
                v2 = __expf(v2); v3 = __expf(v3);
                sum0 += v0 + v1; sum1 += v2 + v3;
            }
            long long o0, o1;
            if (MODE == 2) {
                int h = col >> 6, d0 = col & 63;
                o0 = (long long)(h * 128 + (row >> 4)) * 1024 + ((row & 15) << 6) + d0;
                int row2 = row + 8;
                o1 = (long long)(h * 128 + (row2 >> 4)) * 1024 + ((row2 & 15) << 6) + d0;
            } else {
                o0 = (long long)row * ldC + col;
                o1 = o0 + 8ll * ldC;
            }
            if (HALF_OUT) {
                __half* Cb = (__half*)Cv + bz * sC;
                *(__half2*)(Cb + o0) = __floats2half2_rn(v0, v1);
                *(__half2*)(Cb + o1) = __floats2half2_rn(v2, v3);
            } else {
                float* Cb = (float*)Cv + bz * sC;
                *(float2*)(Cb + o0) = make_float2(v0, v1);
                *(float2*)(Cb + o1) = make_float2(v2, v3);
            }
        }
        if (MODE == 3) {
            sum0 += __shfl_xor_sync(0xffffffffu, sum0, 1);
            sum0 += __shfl_xor_sync(0xffffffffu, sum0, 2);
            sum1 += __shfl_xor_sync(0xffffffffu, sum1, 1);
            sum1 += __shfl_xor_sync(0xffffffffu, sum1, 2);
            if (qc == 0) {
                float* rs = rowsum + bz * 2048;
                atomicAdd(rs + row, sum0);
                atomicAdd(rs + row + 8, sum1);
            }
        }
    }
}

// ---------------------------------------------------------------------------
// persistent DAG kernel: queue of 1792 tile-items, dependency-gated
// ---------------------------------------------------------------------------
__global__ void __launch_bounds__(256, 2) mega(
    const __half* __restrict__ Xh, const __half* __restrict__ Wh,
    const float* __restrict__ bqk, const float* __restrict__ bv,
    const float* __restrict__ bo,
    __half* __restrict__ QK, __half* __restrict__ Vt,
    __half* __restrict__ P, __half* __restrict__ Y,
    float* __restrict__ rsum, int* __restrict__ sync,
    float* __restrict__ out)
{
    __shared__ int s_item;
    int* qhead = sync;
    int* cQK = sync + 1;      // [32] x16
    int* cVt = sync + 33;     // [8]  x32
    int* cS  = sync + 41;     // [32] x16
    int* cPV = sync + 73;     // [16] x16

    for (;;) {
        __syncthreads();
        if (threadIdx.x == 0) s_item = atomicAdd(qhead, 1);
        __syncthreads();
        int it = s_item;
        if (it >= N_ITEMS) return;

        if (it < 512) {
            // QK = Xh @ [Wq;Wk]^T + bqk : gx=16, gy=32
            int bx = it & 15, by = it >> 4;
            gemm_body<0, true>(Xh, 1024, 0, Wh, 1024, 0, bqk, nullptr,
                               QK, 2048, 0, 16, 1.f, bx, by, 0);
            donecnt(&cQK[by]);
        } else if (it < 768) {
            // Vt = Wv @ Xh^T + bv : gx=32, gy=8
            int i2 = it - 512;
            int bx = i2 & 31, by = i2 >> 5;
            gemm_body<1, true>(Wh + 2097152, 1024, 0, Xh, 1024, 0, bv, nullptr,
                               Vt, 4096, 0, 16, 1.f, bx, by, 0);
            donecnt(&cVt[by]);
        } else if (it < 1280) {
            // P = exp(Q @ K^T / 128) : gx=16, gy=16, z=2  (z-major, by, bx)
            int i3 = it - 768;
            int z = i3 >> 8, r = i3 & 255, by = r >> 4, bx = r & 15;
            waitcnt(&cQK[z * 16 + by], 16);
            waitcnt(&cQK[z * 16 + bx], 16);
            gemm_body<3, true>(QK, 2048, 2048ll * 2048, QK + 1024, 2048, 2048ll * 2048,
                               nullptr, rsum, P, 2048, 2048ll * 2048,
                               16, 1.f / 128.f, bx, by, z);
            donecnt(&cS[z * 16 + by]);
        } else if (it < 1536) {
            // Y = (P @ Vt^T)/rowsum shuffled : gx=8, gy=16, z=2 (z, bx, by order)
            int i4 = it - 1280;
            int z = i4 >> 7, r = i4 & 127, bx = r >> 4, by = r & 15;
            waitcnt(&cS[z * 16 + by], 16);
            waitcnt(&cVt[bx], 32);
            gemm_body<2, true>(P, 2048, 2048ll * 2048, Vt, 4096, 2048,
                               nullptr, rsum, Y, 1024, 2048ll * 1024,
                               32, 1.f, bx, by, z);
            donecnt(&cPV[z * 8 + bx]);
        } else {
            // out = Y @ Wo^T + bo : gx=8, gy=32 (by-major so deps match PV order)
            int i5 = it - 1536;
            int by = i5 >> 3, bx = i5 & 7;
            int z = by >> 4, h = by & 15;
            waitcnt(&cPV[z * 8 + (h >> 1)], 16);
            gemm_body<0, false>(Y, 1024, 0, Wh + 3145728, 1024, 0, bo, nullptr,
                                out, 1024, 0, 16, 1.f, bx, by, 0);
        }
    }
}

// ---------------------------------------------------------------------------
// fused fp32->fp16 conversion + bias concat + rowsum/sync zeroing
// ---------------------------------------------------------------------------
__global__ __launch_bounds__(256) void f2h_all(
    const float4* __restrict__ x,
    const float4* __restrict__ w0, const float4* __restrict__ w1,
    const float4* __restrict__ w2, const float4* __restrict__ w3,
    const float* __restrict__ bq, const float* __restrict__ bk,
    __half* __restrict__ Xh, __half* __restrict__ Wh,
    float* __restrict__ bqk, float* __restrict__ rsum, int* __restrict__ sync)
{
    int i = blockIdx.x * 256 + threadIdx.x;
    if (i < 2048) bqk[i] = (i < 1024) ? bq[i] : bk[i - 1024];
    if (i < 4096) rsum[i] = 0.f;
    if (i < 128)  sync[i] = 0;
    const float4* src;
    __half* dst;
    if (i < (1 << 20)) { src = x + i; dst = Xh + (long long)i * 4; }
    else {
        int j = i - (1 << 20);
        int w = j >> 18, off = j & ((1 << 18) - 1);
        const float4* ws[4] = {w0, w1, w2, w3};
        src = ws[w] + off;
        dst = Wh + ((long long)w << 20) + (long long)off * 4;
    }
    float4 v = *src;
    __half2 h0 = __floats2half2_rn(v.x, v.y);
    __half2 h1 = __floats2half2_rn(v.z, v.w);
    *(uint2*)dst = make_uint2(*(uint32_t*)&h0, *(uint32_t*)&h1);
}

// ---------------------------------------------------------------------------
extern "C" void kernel_launch(void* const* d_in, const int* in_sizes, int n_in,
                              void* d_out, int out_size)
{
    const float* x  = (const float*)d_in[0];
    const float* bq = (const float*)d_in[2];
    const float* bk = (const float*)d_in[4];
    const float* bv = (const float*)d_in[6];
    const float* bo = (const float*)d_in[8];
    float* out = (float*)d_out;

    __half *Xh, *Wh, *QK, *Vt, *P, *Y;
    float *bqk, *rsum;
    int *sync;
    cudaGetSymbolAddress((void**)&Xh,   g_Xh);
    cudaGetSymbolAddress((void**)&Wh,   g_Wh);
    cudaGetSymbolAddress((void**)&QK,   g_QK);
    cudaGetSymbolAddress((void**)&Vt,   g_Vt);
    cudaGetSymbolAddress((void**)&P,    g_P);
    cudaGetSymbolAddress((void**)&Y,    g_Y);
    cudaGetSymbolAddress((void**)&bqk,  g_bqk);
    cudaGetSymbolAddress((void**)&rsum, g_rsum);
    cudaGetSymbolAddress((void**)&sync, g_sync);

    int NSM = 148;
    cudaDeviceGetAttribute(&NSM, cudaDevAttrMultiProcessorCount, 0);

    cudaFuncSetAttribute(mega, cudaFuncAttributeMaxDynamicSharedMemorySize, SMEM_TOT);

    f2h_all<<<8192, 256>>>((const float4*)x,
                           (const float4*)d_in[1], (const float4*)d_in[3],
                           (const float4*)d_in[5], (const float4*)d_in[7],
                           bq, bk, Xh, Wh, bqk, rsum, sync);

    mega<<<2 * NSM, 256, SMEM_TOT>>>(Xh, Wh, bqk, bv, bo,
                                     QK, Vt, P, Y, rsum, sync, out);
}